// round 1
// baseline (speedup 1.0000x reference)
#include <cuda_runtime.h>
#include <math.h>

#define B_  4
#define L_  2048
#define D_  1024
#define H_  16
#define DH_ 64
#define M_  (B_*L_)      // 8192
#define BH_ (B_*H_)      // 64
#define SCALE 0.5f       // 1/sqrt(B) quirk from the reference

// ---- static scratch (no allocation allowed in kernel_launch) ----
__device__ float g_Q[(size_t)BH_*L_*DH_];   // [B,H,L,dh] 32MB
__device__ float g_K[(size_t)BH_*L_*DH_];
__device__ float g_V[(size_t)BH_*L_*DH_];
__device__ float g_O[(size_t)M_*D_];        // merged [B,L,D] 32MB
__device__ float g_attn_fallback[(size_t)BH_*L_*L_]; // only used if out_size lacks attn

// ============================================================================
// Generic GEMM: C = X[M x K] @ W[K x N] + bias, 128x128x16 tiles, 8x8/thread.
// HEADSPLIT: write to [B,H,L,dh] layout instead of flat [M,N].
// ============================================================================
template<bool HEADSPLIT>
__global__ __launch_bounds__(256) void gemm_bias_kernel(
    const float* __restrict__ X, const float* __restrict__ W,
    const float* __restrict__ bias, float* __restrict__ out,
    int K, int N)
{
    __shared__ float As[16][132];   // [k][row], padded
    __shared__ float Bs[16][132];   // [k][col], padded
    const int tid = threadIdx.x;
    const int tx = tid & 15, ty = tid >> 4;
    const int bm = blockIdx.y * 128, bn = blockIdx.x * 128;

    float acc[8][8] = {};

    for (int k0 = 0; k0 < K; k0 += 16) {
        #pragma unroll
        for (int i = 0; i < 2; i++) {
            int f = tid + i * 256;
            int r = f >> 2, c = (f & 3) * 4;                 // A: 128 rows x 16 cols
            float4 a = *reinterpret_cast<const float4*>(X + (size_t)(bm + r) * K + k0 + c);
            As[c+0][r] = a.x; As[c+1][r] = a.y; As[c+2][r] = a.z; As[c+3][r] = a.w;
            int rb = f >> 5, cb = (f & 31) * 4;              // B: 16 rows x 128 cols
            float4 b = *reinterpret_cast<const float4*>(W + (size_t)(k0 + rb) * N + bn + cb);
            *reinterpret_cast<float4*>(&Bs[rb][cb]) = b;
        }
        __syncthreads();
        #pragma unroll
        for (int k = 0; k < 16; k++) {
            float ar[8], br[8];
            *(float4*)&ar[0] = *(float4*)&As[k][ty*8];
            *(float4*)&ar[4] = *(float4*)&As[k][ty*8+4];
            *(float4*)&br[0] = *(float4*)&Bs[k][tx*8];
            *(float4*)&br[4] = *(float4*)&Bs[k][tx*8+4];
            #pragma unroll
            for (int i = 0; i < 8; i++)
                #pragma unroll
                for (int j = 0; j < 8; j++)
                    acc[i][j] = fmaf(ar[i], br[j], acc[i][j]);
        }
        __syncthreads();
    }

    #pragma unroll
    for (int i = 0; i < 8; i++) {
        int m = bm + ty*8 + i;
        #pragma unroll
        for (int j = 0; j < 8; j++) {
            int n = bn + tx*8 + j;
            float v = acc[i][j] + bias[n];
            if (HEADSPLIT) {
                int b = m >> 11, l = m & (L_ - 1);
                int h = n >> 6,  dh = n & 63;
                out[(((size_t)(b*H_ + h))*L_ + l)*DH_ + dh] = v;
            } else {
                out[(size_t)m * N + n] = v;
            }
        }
    }
}

// ============================================================================
// Scores: per (b,h)  S = SCALE * Qh @ Kh^T   (M=N=2048, K=64)
// ============================================================================
__global__ __launch_bounds__(256) void scores_kernel(float* __restrict__ attn)
{
    const int bh = blockIdx.z;
    const float* Qp = g_Q + (size_t)bh * L_ * DH_;
    const float* Kp = g_K + (size_t)bh * L_ * DH_;
    __shared__ float As[16][132];
    __shared__ float Bs[16][132];
    const int tid = threadIdx.x;
    const int tx = tid & 15, ty = tid >> 4;
    const int bm = blockIdx.y * 128, bn = blockIdx.x * 128;

    float acc[8][8] = {};

    for (int k0 = 0; k0 < DH_; k0 += 16) {
        #pragma unroll
        for (int i = 0; i < 2; i++) {
            int f = tid + i * 256;
            int r = f >> 2, c = (f & 3) * 4;   // both tiles: 128 rows x 16 k-cols
            float4 a = *reinterpret_cast<const float4*>(Qp + (size_t)(bm + r) * DH_ + k0 + c);
            As[c+0][r] = a.x; As[c+1][r] = a.y; As[c+2][r] = a.z; As[c+3][r] = a.w;
            float4 b = *reinterpret_cast<const float4*>(Kp + (size_t)(bn + r) * DH_ + k0 + c);
            Bs[c+0][r] = b.x; Bs[c+1][r] = b.y; Bs[c+2][r] = b.z; Bs[c+3][r] = b.w;
        }
        __syncthreads();
        #pragma unroll
        for (int k = 0; k < 16; k++) {
            float ar[8], br[8];
            *(float4*)&ar[0] = *(float4*)&As[k][ty*8];
            *(float4*)&ar[4] = *(float4*)&As[k][ty*8+4];
            *(float4*)&br[0] = *(float4*)&Bs[k][tx*8];
            *(float4*)&br[4] = *(float4*)&Bs[k][tx*8+4];
            #pragma unroll
            for (int i = 0; i < 8; i++)
                #pragma unroll
                for (int j = 0; j < 8; j++)
                    acc[i][j] = fmaf(ar[i], br[j], acc[i][j]);
        }
        __syncthreads();
    }

    float* rowbase = attn + ((size_t)bh * L_ + bm) * L_ + bn;
    #pragma unroll
    for (int i = 0; i < 8; i++) {
        #pragma unroll
        for (int j = 0; j < 8; j++) {
            rowbase[(size_t)(ty*8 + i) * L_ + tx*8 + j] = acc[i][j] * SCALE;
        }
    }
}

// ============================================================================
// Row softmax in place, one block per row of 2048.
// ============================================================================
__global__ __launch_bounds__(256) void softmax_kernel(float* __restrict__ attn)
{
    float* p = attn + (size_t)blockIdx.x * L_;
    const int t = threadIdx.x;
    float v[8];
    float m = -1e30f;
    #pragma unroll
    for (int i = 0; i < 8; i++) { v[i] = p[t + i*256]; m = fmaxf(m, v[i]); }
    #pragma unroll
    for (int o = 16; o; o >>= 1) m = fmaxf(m, __shfl_xor_sync(0xffffffffu, m, o));
    __shared__ float redm[8];
    __shared__ float reds[8];
    if ((t & 31) == 0) redm[t >> 5] = m;
    __syncthreads();
    float bm = redm[0];
    #pragma unroll
    for (int w = 1; w < 8; w++) bm = fmaxf(bm, redm[w]);

    float s = 0.f;
    #pragma unroll
    for (int i = 0; i < 8; i++) { v[i] = __expf(v[i] - bm); s += v[i]; }
    #pragma unroll
    for (int o = 16; o; o >>= 1) s += __shfl_xor_sync(0xffffffffu, s, o);
    if ((t & 31) == 0) reds[t >> 5] = s;
    __syncthreads();
    float bs = 0.f;
    #pragma unroll
    for (int w = 0; w < 8; w++) bs += reds[w];
    float inv = 1.0f / bs;
    #pragma unroll
    for (int i = 0; i < 8; i++) p[t + i*256] = v[i] * inv;
}

// ============================================================================
// PV: per (b,h)  O = attn @ Vh   (M=2048, N=64, K=2048), 128x64x16 tiles
// output written merged into g_O [B,L,D]
// ============================================================================
__global__ __launch_bounds__(256) void pv_kernel(const float* __restrict__ attn)
{
    const int bh = blockIdx.y;
    const float* A  = attn + (size_t)bh * L_ * L_;
    const float* Vp = g_V  + (size_t)bh * L_ * DH_;
    const int bm = blockIdx.x * 128;
    __shared__ float As[16][132];
    __shared__ float Bs[16][68];
    const int tid = threadIdx.x;
    const int tx = tid & 15, ty = tid >> 4;

    float acc[8][4] = {};

    for (int k0 = 0; k0 < L_; k0 += 16) {
        #pragma unroll
        for (int i = 0; i < 2; i++) {
            int f = tid + i * 256;
            int r = f >> 2, c = (f & 3) * 4;
            float4 a = *reinterpret_cast<const float4*>(A + (size_t)(bm + r) * L_ + k0 + c);
            As[c+0][r] = a.x; As[c+1][r] = a.y; As[c+2][r] = a.z; As[c+3][r] = a.w;
        }
        {
            int rb = tid >> 4, cb = (tid & 15) * 4;          // 16 x 64
            float4 b = *reinterpret_cast<const float4*>(Vp + (size_t)(k0 + rb) * DH_ + cb);
            *reinterpret_cast<float4*>(&Bs[rb][cb]) = b;
        }
        __syncthreads();
        #pragma unroll
        for (int k = 0; k < 16; k++) {
            float ar[8], br[4];
            *(float4*)&ar[0] = *(float4*)&As[k][ty*8];
            *(float4*)&ar[4] = *(float4*)&As[k][ty*8+4];
            *(float4*)&br[0] = *(float4*)&Bs[k][tx*4];
            #pragma unroll
            for (int i = 0; i < 8; i++)
                #pragma unroll
                for (int j = 0; j < 4; j++)
                    acc[i][j] = fmaf(ar[i], br[j], acc[i][j]);
        }
        __syncthreads();
    }

    const int b = bh >> 4, h = bh & 15;
    #pragma unroll
    for (int i = 0; i < 8; i++) {
        int m = bm + ty*8 + i;
        #pragma unroll
        for (int j = 0; j < 4; j++) {
            g_O[((size_t)(b*L_ + m))*D_ + h*DH_ + tx*4 + j] = acc[i][j];
        }
    }
}

// ============================================================================
extern "C" void kernel_launch(void* const* d_in, const int* in_sizes, int n_in,
                              void* d_out, int out_size)
{
    const float* q  = (const float*)d_in[0];
    const float* k  = (const float*)d_in[1];
    const float* v  = (const float*)d_in[2];
    const float* Wq = (const float*)d_in[3];
    const float* bq = (const float*)d_in[4];
    const float* Wk = (const float*)d_in[5];
    const float* bk = (const float*)d_in[6];
    const float* Wv = (const float*)d_in[7];
    const float* bv = (const float*)d_in[8];
    const float* Wo = (const float*)d_in[9];
    const float* bo = (const float*)d_in[10];
    float* out = (float*)d_out;

    float *pQ, *pK, *pV, *pO, *pAttnFb;
    cudaGetSymbolAddress((void**)&pQ, g_Q);
    cudaGetSymbolAddress((void**)&pK, g_K);
    cudaGetSymbolAddress((void**)&pV, g_V);
    cudaGetSymbolAddress((void**)&pO, g_O);
    cudaGetSymbolAddress((void**)&pAttnFb, g_attn_fallback);

    // Output is (out, attn) flattened when out_size covers both; otherwise
    // attn lives in static scratch and only `out` is written to d_out.
    const long long need = (long long)M_ * D_ + (long long)BH_ * L_ * L_;
    float* attn = ((long long)out_size >= need) ? (out + (size_t)M_ * D_) : pAttnFb;

    dim3 gProj(D_/128, M_/128);            // (8, 64)
    gemm_bias_kernel<true><<<gProj, 256>>>(q, Wq, bq, pQ, D_, D_);
    gemm_bias_kernel<true><<<gProj, 256>>>(k, Wk, bk, pK, D_, D_);
    gemm_bias_kernel<true><<<gProj, 256>>>(v, Wv, bv, pV, D_, D_);

    dim3 gS(L_/128, L_/128, BH_);          // (16,16,64)
    scores_kernel<<<gS, 256>>>(attn);

    softmax_kernel<<<BH_*L_, 256>>>(attn); // 131072 rows

    dim3 gPV(L_/128, BH_);                 // (16, 64)
    pv_kernel<<<gPV, 256>>>(attn);

    gemm_bias_kernel<false><<<gProj, 256>>>(pO, Wo, bo, out, D_, D_);
}

// round 2
// speedup vs baseline: 1.0005x; 1.0005x over previous
#include <cuda_runtime.h>
#include <math.h>

#define B_  4
#define L_  2048
#define D_  1024
#define H_  16
#define DH_ 64
#define M_  (B_*L_)      // 8192
#define BH_ (B_*H_)      // 64
#define SCALE 0.5f       // 1/sqrt(B) quirk from the reference

// ---- static scratch (no allocation allowed in kernel_launch) ----
__device__ float g_Q[(size_t)BH_*L_*DH_];   // [B,H,L,dh] 32MB
__device__ float g_K[(size_t)BH_*L_*DH_];
__device__ float g_V[(size_t)BH_*L_*DH_];
__device__ float g_O[(size_t)M_*D_];        // merged [B,L,D] 32MB
__device__ float g_attn_fallback[(size_t)BH_*L_*L_]; // only used if out_size lacks attn

// ============================================================================
// Generic GEMM: C = X[M x K] @ W[K x N] + bias, 128x128x16 tiles, 8x8/thread.
// HEADSPLIT: write to [B,H,L,dh] layout instead of flat [M,N].
// ============================================================================
template<bool HEADSPLIT>
__global__ __launch_bounds__(256) void gemm_bias_kernel(
    const float* __restrict__ X, const float* __restrict__ W,
    const float* __restrict__ bias, float* __restrict__ out,
    int K, int N)
{
    __shared__ float As[16][132];   // [k][row], padded
    __shared__ float Bs[16][132];   // [k][col], padded
    const int tid = threadIdx.x;
    const int tx = tid & 15, ty = tid >> 4;
    const int bm = blockIdx.y * 128, bn = blockIdx.x * 128;

    float acc[8][8] = {};

    for (int k0 = 0; k0 < K; k0 += 16) {
        #pragma unroll
        for (int i = 0; i < 2; i++) {
            int f = tid + i * 256;
            int r = f >> 2, c = (f & 3) * 4;                 // A: 128 rows x 16 cols
            float4 a = *reinterpret_cast<const float4*>(X + (size_t)(bm + r) * K + k0 + c);
            As[c+0][r] = a.x; As[c+1][r] = a.y; As[c+2][r] = a.z; As[c+3][r] = a.w;
            int rb = f >> 5, cb = (f & 31) * 4;              // B: 16 rows x 128 cols
            float4 b = *reinterpret_cast<const float4*>(W + (size_t)(k0 + rb) * N + bn + cb);
            *reinterpret_cast<float4*>(&Bs[rb][cb]) = b;
        }
        __syncthreads();
        #pragma unroll
        for (int k = 0; k < 16; k++) {
            float ar[8], br[8];
            *(float4*)&ar[0] = *(float4*)&As[k][ty*8];
            *(float4*)&ar[4] = *(float4*)&As[k][ty*8+4];
            *(float4*)&br[0] = *(float4*)&Bs[k][tx*8];
            *(float4*)&br[4] = *(float4*)&Bs[k][tx*8+4];
            #pragma unroll
            for (int i = 0; i < 8; i++)
                #pragma unroll
                for (int j = 0; j < 8; j++)
                    acc[i][j] = fmaf(ar[i], br[j], acc[i][j]);
        }
        __syncthreads();
    }

    #pragma unroll
    for (int i = 0; i < 8; i++) {
        int m = bm + ty*8 + i;
        #pragma unroll
        for (int j = 0; j < 8; j++) {
            int n = bn + tx*8 + j;
            float v = acc[i][j] + bias[n];
            if (HEADSPLIT) {
                int b = m >> 11, l = m & (L_ - 1);
                int h = n >> 6,  dh = n & 63;
                out[(((size_t)(b*H_ + h))*L_ + l)*DH_ + dh] = v;
            } else {
                out[(size_t)m * N + n] = v;
            }
        }
    }
}

// ============================================================================
// Scores: per (b,h)  S = SCALE * Qh @ Kh^T   (M=N=2048, K=64)
// ============================================================================
__global__ __launch_bounds__(256) void scores_kernel(float* __restrict__ attn)
{
    const int bh = blockIdx.z;
    const float* Qp = g_Q + (size_t)bh * L_ * DH_;
    const float* Kp = g_K + (size_t)bh * L_ * DH_;
    __shared__ float As[16][132];
    __shared__ float Bs[16][132];
    const int tid = threadIdx.x;
    const int tx = tid & 15, ty = tid >> 4;
    const int bm = blockIdx.y * 128, bn = blockIdx.x * 128;

    float acc[8][8] = {};

    for (int k0 = 0; k0 < DH_; k0 += 16) {
        #pragma unroll
        for (int i = 0; i < 2; i++) {
            int f = tid + i * 256;
            int r = f >> 2, c = (f & 3) * 4;   // both tiles: 128 rows x 16 k-cols
            float4 a = *reinterpret_cast<const float4*>(Qp + (size_t)(bm + r) * DH_ + k0 + c);
            As[c+0][r] = a.x; As[c+1][r] = a.y; As[c+2][r] = a.z; As[c+3][r] = a.w;
            float4 b = *reinterpret_cast<const float4*>(Kp + (size_t)(bn + r) * DH_ + k0 + c);
            Bs[c+0][r] = b.x; Bs[c+1][r] = b.y; Bs[c+2][r] = b.z; Bs[c+3][r] = b.w;
        }
        __syncthreads();
        #pragma unroll
        for (int k = 0; k < 16; k++) {
            float ar[8], br[8];
            *(float4*)&ar[0] = *(float4*)&As[k][ty*8];
            *(float4*)&ar[4] = *(float4*)&As[k][ty*8+4];
            *(float4*)&br[0] = *(float4*)&Bs[k][tx*8];
            *(float4*)&br[4] = *(float4*)&Bs[k][tx*8+4];
            #pragma unroll
            for (int i = 0; i < 8; i++)
                #pragma unroll
                for (int j = 0; j < 8; j++)
                    acc[i][j] = fmaf(ar[i], br[j], acc[i][j]);
        }
        __syncthreads();
    }

    float* rowbase = attn + ((size_t)bh * L_ + bm) * L_ + bn;
    #pragma unroll
    for (int i = 0; i < 8; i++) {
        #pragma unroll
        for (int j = 0; j < 8; j++) {
            rowbase[(size_t)(ty*8 + i) * L_ + tx*8 + j] = acc[i][j] * SCALE;
        }
    }
}

// ============================================================================
// Row softmax in place, one block per row of 2048.
// ============================================================================
__global__ __launch_bounds__(256) void softmax_kernel(float* __restrict__ attn)
{
    float* p = attn + (size_t)blockIdx.x * L_;
    const int t = threadIdx.x;
    float v[8];
    float m = -1e30f;
    #pragma unroll
    for (int i = 0; i < 8; i++) { v[i] = p[t + i*256]; m = fmaxf(m, v[i]); }
    #pragma unroll
    for (int o = 16; o; o >>= 1) m = fmaxf(m, __shfl_xor_sync(0xffffffffu, m, o));
    __shared__ float redm[8];
    __shared__ float reds[8];
    if ((t & 31) == 0) redm[t >> 5] = m;
    __syncthreads();
    float bm = redm[0];
    #pragma unroll
    for (int w = 1; w < 8; w++) bm = fmaxf(bm, redm[w]);

    float s = 0.f;
    #pragma unroll
    for (int i = 0; i < 8; i++) { v[i] = __expf(v[i] - bm); s += v[i]; }
    #pragma unroll
    for (int o = 16; o; o >>= 1) s += __shfl_xor_sync(0xffffffffu, s, o);
    if ((t & 31) == 0) reds[t >> 5] = s;
    __syncthreads();
    float bs = 0.f;
    #pragma unroll
    for (int w = 0; w < 8; w++) bs += reds[w];
    float inv = 1.0f / bs;
    #pragma unroll
    for (int i = 0; i < 8; i++) p[t + i*256] = v[i] * inv;
}

// ============================================================================
// PV: per (b,h)  O = attn @ Vh   (M=2048, N=64, K=2048), 128x64x16 tiles
// output written merged into g_O [B,L,D]
// ============================================================================
__global__ __launch_bounds__(256) void pv_kernel(const float* __restrict__ attn)
{
    const int bh = blockIdx.y;
    const float* A  = attn + (size_t)bh * L_ * L_;
    const float* Vp = g_V  + (size_t)bh * L_ * DH_;
    const int bm = blockIdx.x * 128;
    __shared__ float As[16][132];
    __shared__ float Bs[16][68];
    const int tid = threadIdx.x;
    const int tx = tid & 15, ty = tid >> 4;

    float acc[8][4] = {};

    for (int k0 = 0; k0 < L_; k0 += 16) {
        #pragma unroll
        for (int i = 0; i < 2; i++) {
            int f = tid + i * 256;
            int r = f >> 2, c = (f & 3) * 4;
            float4 a = *reinterpret_cast<const float4*>(A + (size_t)(bm + r) * L_ + k0 + c);
            As[c+0][r] = a.x; As[c+1][r] = a.y; As[c+2][r] = a.z; As[c+3][r] = a.w;
        }
        {
            int rb = tid >> 4, cb = (tid & 15) * 4;          // 16 x 64
            float4 b = *reinterpret_cast<const float4*>(Vp + (size_t)(k0 + rb) * DH_ + cb);
            *reinterpret_cast<float4*>(&Bs[rb][cb]) = b;
        }
        __syncthreads();
        #pragma unroll
        for (int k = 0; k < 16; k++) {
            float ar[8], br[4];
            *(float4*)&ar[0] = *(float4*)&As[k][ty*8];
            *(float4*)&ar[4] = *(float4*)&As[k][ty*8+4];
            *(float4*)&br[0] = *(float4*)&Bs[k][tx*4];
            #pragma unroll
            for (int i = 0; i < 8; i++)
                #pragma unroll
                for (int j = 0; j < 4; j++)
                    acc[i][j] = fmaf(ar[i], br[j], acc[i][j]);
        }
        __syncthreads();
    }

    const int b = bh >> 4, h = bh & 15;
    #pragma unroll
    for (int i = 0; i < 8; i++) {
        int m = bm + ty*8 + i;
        #pragma unroll
        for (int j = 0; j < 4; j++) {
            g_O[((size_t)(b*L_ + m))*D_ + h*DH_ + tx*4 + j] = acc[i][j];
        }
    }
}

// ============================================================================
extern "C" void kernel_launch(void* const* d_in, const int* in_sizes, int n_in,
                              void* d_out, int out_size)
{
    const float* q  = (const float*)d_in[0];
    const float* k  = (const float*)d_in[1];
    const float* v  = (const float*)d_in[2];
    const float* Wq = (const float*)d_in[3];
    const float* bq = (const float*)d_in[4];
    const float* Wk = (const float*)d_in[5];
    const float* bk = (const float*)d_in[6];
    const float* Wv = (const float*)d_in[7];
    const float* bv = (const float*)d_in[8];
    const float* Wo = (const float*)d_in[9];
    const float* bo = (const float*)d_in[10];
    float* out = (float*)d_out;

    float *pQ, *pK, *pV, *pO, *pAttnFb;
    cudaGetSymbolAddress((void**)&pQ, g_Q);
    cudaGetSymbolAddress((void**)&pK, g_K);
    cudaGetSymbolAddress((void**)&pV, g_V);
    cudaGetSymbolAddress((void**)&pO, g_O);
    cudaGetSymbolAddress((void**)&pAttnFb, g_attn_fallback);

    // Output is (out, attn) flattened when out_size covers both; otherwise
    // attn lives in static scratch and only `out` is written to d_out.
    const long long need = (long long)M_ * D_ + (long long)BH_ * L_ * L_;
    float* attn = ((long long)out_size >= need) ? (out + (size_t)M_ * D_) : pAttnFb;

    dim3 gProj(D_/128, M_/128);            // (8, 64)
    gemm_bias_kernel<true><<<gProj, 256>>>(q, Wq, bq, pQ, D_, D_);
    gemm_bias_kernel<true><<<gProj, 256>>>(k, Wk, bk, pK, D_, D_);
    gemm_bias_kernel<true><<<gProj, 256>>>(v, Wv, bv, pV, D_, D_);

    dim3 gS(L_/128, L_/128, BH_);          // (16,16,64)
    scores_kernel<<<gS, 256>>>(attn);

    softmax_kernel<<<BH_*L_, 256>>>(attn); // 131072 rows

    dim3 gPV(L_/128, BH_);                 // (16, 64)
    pv_kernel<<<gPV, 256>>>(attn);

    gemm_bias_kernel<false><<<gProj, 256>>>(pO, Wo, bo, out, D_, D_);
}

// round 5
// speedup vs baseline: 1.9157x; 1.9147x over previous
#include <cuda_runtime.h>
#include <cuda_bf16.h>
#include <mma.h>
#include <stdint.h>

using namespace nvcuda;

#define B_  4
#define L_  2048
#define D_  1024
#define H_  16
#define DH_ 64
#define M_  (B_*L_)
#define BH_ (B_*H_)
#define SCALE 0.5f

typedef __nv_bfloat16 bf16;

// ---------------- static scratch ----------------
__device__ float g_O[(size_t)M_*D_];
__device__ bf16 g_Qh[(size_t)BH_*L_*DH_];
__device__ bf16 g_Ql[(size_t)BH_*L_*DH_];
__device__ bf16 g_Kh[(size_t)BH_*L_*DH_];
__device__ bf16 g_Kl[(size_t)BH_*L_*DH_];
__device__ bf16 g_Vh[(size_t)BH_*L_*DH_];
__device__ bf16 g_Vl[(size_t)BH_*L_*DH_];
__device__ bf16 g_Wth[4][(size_t)D_*D_];    // W^T hi: [n][k]
__device__ bf16 g_Wtl[4][(size_t)D_*D_];
__device__ float g_attn_fallback[(size_t)BH_*L_*L_];

__device__ __forceinline__ void split1(float x, unsigned short& h, unsigned short& l){
    bf16 hb = __float2bfloat16(x);
    float r = x - __bfloat162float(hb);
    bf16 lb = __float2bfloat16(r);
    h = __bfloat16_as_ushort(hb);
    l = __bfloat16_as_ushort(lb);
}

// fp32 [128 rows x 32 k] -> split hi/lo bf16 smem tiles, pitch 48 elements
__device__ __forceinline__ void load_a_split(int tid, const float* __restrict__ X, int ldx,
                                             int row0, int k0, bf16* dh, bf16* dl){
    #pragma unroll
    for (int i = 0; i < 4; i++) {
        int e = tid + i*256;
        int m = e >> 3, k4 = (e & 7) << 2;
        float4 v = *(const float4*)(X + (size_t)(row0+m)*ldx + k0 + k4);
        unsigned short h0,h1,h2,h3,l0,l1,l2,l3;
        split1(v.x,h0,l0); split1(v.y,h1,l1); split1(v.z,h2,l2); split1(v.w,h3,l3);
        uint2 hp = make_uint2((uint32_t)h0 | ((uint32_t)h1<<16), (uint32_t)h2 | ((uint32_t)h3<<16));
        uint2 lp = make_uint2((uint32_t)l0 | ((uint32_t)l1<<16), (uint32_t)l2 | ((uint32_t)l3<<16));
        *(uint2*)(dh + m*48 + k4) = hp;
        *(uint2*)(dl + m*48 + k4) = lp;
    }
}

// bf16 [128 rows x 32 k] copy, pitch 48  (512 uint4 chunks -> 2 iterations)
__device__ __forceinline__ void load_rows_bf16(int tid, const bf16* __restrict__ G, int ld,
                                               int row0, int k0, bf16* dst){
    #pragma unroll
    for (int i = 0; i < 2; i++) {
        int e = tid + i*256;
        int rr = e >> 2, o = e & 3;
        uint4 v = *(const uint4*)(G + (size_t)(row0+rr)*ld + k0 + o*8);
        *(uint4*)(dst + rr*48 + o*8) = v;
    }
}

// bf16 [32 rows x 64 n] copy (V tile, row-major), pitch 80
__device__ __forceinline__ void load_v_bf16(int tid, const bf16* __restrict__ G,
                                            int k0, bf16* dst){
    int rr = tid >> 3, o = tid & 7;
    uint4 v = *(const uint4*)(G + (size_t)(k0+rr)*DH_ + o*8);
    *(uint4*)(dst + rr*80 + o*8) = v;
}

// ============================================================================
// Weight split+transpose: W[k][n] fp32 -> W^T hi/lo [n][k] bf16
// ============================================================================
__global__ __launch_bounds__(256) void split_w_kernel(const float* __restrict__ W,
                                                      bf16* __restrict__ oh,
                                                      bf16* __restrict__ ol){
    __shared__ float s[32][33];
    const int bk = blockIdx.x*32, bn = blockIdx.y*32;
    const int tx = threadIdx.x & 31, ty = threadIdx.x >> 5;
    #pragma unroll
    for (int i = 0; i < 4; i++)
        s[ty + i*8][tx] = W[(size_t)(bk + ty + i*8)*D_ + bn + tx];
    __syncthreads();
    #pragma unroll
    for (int i = 0; i < 4; i++) {
        float v = s[tx][ty + i*8];
        unsigned short h, l; split1(v, h, l);
        size_t a = (size_t)(bn + ty + i*8)*D_ + bk + tx;
        oh[a] = __ushort_as_bfloat16(h);
        ol[a] = __ushort_as_bfloat16(l);
    }
}

// ============================================================================
// Projection GEMM: C[128x128] = X[M,1024] @ W[1024,1024] + bias
// 8 warps (2 m x 4 n), warp tile 64x32. MODE 0: head-split hi/lo. MODE 2: fp32.
// ============================================================================
template<int MODE>
__global__ __launch_bounds__(256, 2) void proj_mma(
    const float* __restrict__ X,
    const bf16* __restrict__ Wth, const bf16* __restrict__ Wtl,
    const float* __restrict__ bias,
    bf16* __restrict__ outH, bf16* __restrict__ outL, float* __restrict__ outF)
{
    extern __shared__ char sm[];
    bf16* Ah = (bf16*)sm;           // [128][48]
    bf16* Al = Ah + 128*48;
    bf16* Bh = Al + 128*48;
    bf16* Bl = Bh + 128*48;
    const int tid = threadIdx.x, w = tid >> 5, lid = tid & 31;
    const int wm = w >> 2, wn = w & 3;            // 2 x 4
    const int bm = blockIdx.y * 128, bn = blockIdx.x * 128;

    wmma::fragment<wmma::accumulator, 16, 16, 16, float> acc[4][2];
    #pragma unroll
    for (int i = 0; i < 4; i++)
        #pragma unroll
        for (int j = 0; j < 2; j++)
            wmma::fill_fragment(acc[i][j], 0.0f);

    for (int t = 0; t < 32; t++) {
        load_a_split(tid, X, D_, bm, t*32, Ah, Al);
        load_rows_bf16(tid, Wth, D_, bn, t*32, Bh);
        load_rows_bf16(tid, Wtl, D_, bn, t*32, Bl);
        __syncthreads();
        #pragma unroll
        for (int ks = 0; ks < 32; ks += 16) {
            wmma::fragment<wmma::matrix_b, 16, 16, 16, bf16, wmma::col_major> fbh[2], fbl[2];
            #pragma unroll
            for (int j = 0; j < 2; j++) {
                wmma::load_matrix_sync(fbh[j], Bh + (wn*32 + j*16)*48 + ks, 48);
                wmma::load_matrix_sync(fbl[j], Bl + (wn*32 + j*16)*48 + ks, 48);
            }
            #pragma unroll
            for (int i = 0; i < 4; i++) {
                wmma::fragment<wmma::matrix_a, 16, 16, 16, bf16, wmma::row_major> fah, fal;
                wmma::load_matrix_sync(fah, Ah + (wm*64 + i*16)*48 + ks, 48);
                wmma::load_matrix_sync(fal, Al + (wm*64 + i*16)*48 + ks, 48);
                #pragma unroll
                for (int j = 0; j < 2; j++) {
                    wmma::mma_sync(acc[i][j], fah, fbh[j], acc[i][j]);
                    wmma::mma_sync(acc[i][j], fah, fbl[j], acc[i][j]);
                    wmma::mma_sync(acc[i][j], fal, fbh[j], acc[i][j]);
                }
            }
        }
        __syncthreads();
    }

    // epilogue: per-warp 16x16 staging (pitch 24 f32), reuse tile smem
    float* ws = (float*)sm + w * (16*24);
    #pragma unroll
    for (int i = 0; i < 4; i++) {
        #pragma unroll
        for (int j = 0; j < 2; j++) {
            wmma::store_matrix_sync(ws, acc[i][j], 24, wmma::mem_row_major);
            __syncwarp();
            #pragma unroll
            for (int tt = 0; tt < 8; tt++) {
                int e = lid + tt*32, r = e >> 4, c = e & 15;
                int m = bm + wm*64 + i*16 + r;
                int n = bn + wn*32 + j*16 + c;
                float v = ws[r*24 + c] + bias[n];
                if (MODE == 0) {
                    unsigned short hs, ls; split1(v, hs, ls);
                    int bb = m >> 11, l = m & (L_-1), h = n >> 6, dh = n & 63;
                    size_t a = (((size_t)(bb*H_ + h))*L_ + l)*DH_ + dh;
                    outH[a] = __ushort_as_bfloat16(hs);
                    outL[a] = __ushort_as_bfloat16(ls);
                } else {
                    outF[(size_t)m*D_ + n] = v;
                }
            }
            __syncwarp();
        }
    }
}

// ============================================================================
// Scores: attn_raw[bh] = SCALE * Q @ K^T, tile 128x128, K=64 (2 chunks of 32)
// ============================================================================
__global__ __launch_bounds__(256, 2) void scores_mma(float* __restrict__ attn)
{
    extern __shared__ char sm[];
    bf16* Ah = (bf16*)sm;
    bf16* Al = Ah + 128*48;
    bf16* Bh = Al + 128*48;
    bf16* Bl = Bh + 128*48;
    const int tid = threadIdx.x, w = tid >> 5, lid = tid & 31;
    const int wm = w >> 2, wn = w & 3;
    const int bh = blockIdx.z, bm = blockIdx.y * 128, bn = blockIdx.x * 128;
    const size_t qo = (size_t)bh * L_ * DH_;

    wmma::fragment<wmma::accumulator, 16, 16, 16, float> acc[4][2];
    #pragma unroll
    for (int i = 0; i < 4; i++)
        #pragma unroll
        for (int j = 0; j < 2; j++)
            wmma::fill_fragment(acc[i][j], 0.0f);

    #pragma unroll
    for (int t = 0; t < 2; t++) {
        load_rows_bf16(tid, g_Qh + qo, DH_, bm, t*32, Ah);
        load_rows_bf16(tid, g_Ql + qo, DH_, bm, t*32, Al);
        load_rows_bf16(tid, g_Kh + qo, DH_, bn, t*32, Bh);
        load_rows_bf16(tid, g_Kl + qo, DH_, bn, t*32, Bl);
        __syncthreads();
        #pragma unroll
        for (int ks = 0; ks < 32; ks += 16) {
            wmma::fragment<wmma::matrix_b, 16, 16, 16, bf16, wmma::col_major> fbh[2], fbl[2];
            #pragma unroll
            for (int j = 0; j < 2; j++) {
                wmma::load_matrix_sync(fbh[j], Bh + (wn*32 + j*16)*48 + ks, 48);
                wmma::load_matrix_sync(fbl[j], Bl + (wn*32 + j*16)*48 + ks, 48);
            }
            #pragma unroll
            for (int i = 0; i < 4; i++) {
                wmma::fragment<wmma::matrix_a, 16, 16, 16, bf16, wmma::row_major> fah, fal;
                wmma::load_matrix_sync(fah, Ah + (wm*64 + i*16)*48 + ks, 48);
                wmma::load_matrix_sync(fal, Al + (wm*64 + i*16)*48 + ks, 48);
                #pragma unroll
                for (int j = 0; j < 2; j++) {
                    wmma::mma_sync(acc[i][j], fah, fbh[j], acc[i][j]);
                    wmma::mma_sync(acc[i][j], fah, fbl[j], acc[i][j]);
                    wmma::mma_sync(acc[i][j], fal, fbh[j], acc[i][j]);
                }
            }
        }
        __syncthreads();
    }

    float* ws = (float*)sm + w * (16*24);
    #pragma unroll
    for (int i = 0; i < 4; i++) {
        #pragma unroll
        for (int j = 0; j < 2; j++) {
            wmma::store_matrix_sync(ws, acc[i][j], 24, wmma::mem_row_major);
            __syncwarp();
            #pragma unroll
            for (int tt = 0; tt < 8; tt++) {
                int e = lid + tt*32, r = e >> 4, c = e & 15;
                int m = bm + wm*64 + i*16 + r;
                int n = bn + wn*32 + j*16 + c;
                attn[((size_t)bh*L_ + m)*L_ + n] = ws[r*24 + c] * SCALE;
            }
            __syncwarp();
        }
    }
}

// ============================================================================
// Softmax, one block per row
// ============================================================================
__global__ __launch_bounds__(256) void softmax_kernel(float* __restrict__ attn)
{
    float* p = attn + (size_t)blockIdx.x * L_;
    const int t = threadIdx.x;
    float v[8];
    float m = -1e30f;
    #pragma unroll
    for (int i = 0; i < 8; i++) { v[i] = p[t + i*256]; m = fmaxf(m, v[i]); }
    #pragma unroll
    for (int o = 16; o; o >>= 1) m = fmaxf(m, __shfl_xor_sync(0xffffffffu, m, o));
    __shared__ float redm[8], reds[8];
    if ((t & 31) == 0) redm[t >> 5] = m;
    __syncthreads();
    float bm = redm[0];
    #pragma unroll
    for (int q = 1; q < 8; q++) bm = fmaxf(bm, redm[q]);
    float s = 0.f;
    #pragma unroll
    for (int i = 0; i < 8; i++) { v[i] = __expf(v[i] - bm); s += v[i]; }
    #pragma unroll
    for (int o = 16; o; o >>= 1) s += __shfl_xor_sync(0xffffffffu, s, o);
    if ((t & 31) == 0) reds[t >> 5] = s;
    __syncthreads();
    float bs = 0.f;
    #pragma unroll
    for (int q = 0; q < 8; q++) bs += reds[q];
    float inv = 1.0f / bs;
    #pragma unroll
    for (int i = 0; i < 8; i++) p[t + i*256] = v[i] * inv;
}

// ============================================================================
// PV: O[128x64] = attn[128x2048] @ V[2048x64] per (bh, m-tile)
// 8 warps (4 m x 2 n), warp tile 32x32.
// ============================================================================
__global__ __launch_bounds__(256, 2) void pv_mma(const float* __restrict__ attn)
{
    extern __shared__ char sm[];
    bf16* Ph = (bf16*)sm;            // [128][48]
    bf16* Pl = Ph + 128*48;
    bf16* Vh = Pl + 128*48;          // [32][80]
    bf16* Vl = Vh + 32*80;
    const int tid = threadIdx.x, w = tid >> 5, lid = tid & 31;
    const int wm = w >> 1, wn = w & 1;            // 4 x 2
    const int bh = blockIdx.y, bm = blockIdx.x * 128;
    const float* A = attn + (size_t)bh * L_ * L_;
    const bf16* Vgh = g_Vh + (size_t)bh * L_ * DH_;
    const bf16* Vgl = g_Vl + (size_t)bh * L_ * DH_;

    wmma::fragment<wmma::accumulator, 16, 16, 16, float> acc[2][2];
    #pragma unroll
    for (int i = 0; i < 2; i++)
        #pragma unroll
        for (int j = 0; j < 2; j++)
            wmma::fill_fragment(acc[i][j], 0.0f);

    for (int t = 0; t < 64; t++) {
        load_a_split(tid, A, L_, bm, t*32, Ph, Pl);
        load_v_bf16(tid, Vgh, t*32, Vh);
        load_v_bf16(tid, Vgl, t*32, Vl);
        __syncthreads();
        #pragma unroll
        for (int ks = 0; ks < 32; ks += 16) {
            wmma::fragment<wmma::matrix_b, 16, 16, 16, bf16, wmma::row_major> fbh[2], fbl[2];
            #pragma unroll
            for (int j = 0; j < 2; j++) {
                wmma::load_matrix_sync(fbh[j], Vh + ks*80 + wn*32 + j*16, 80);
                wmma::load_matrix_sync(fbl[j], Vl + ks*80 + wn*32 + j*16, 80);
            }
            #pragma unroll
            for (int i = 0; i < 2; i++) {
                wmma::fragment<wmma::matrix_a, 16, 16, 16, bf16, wmma::row_major> fah, fal;
                wmma::load_matrix_sync(fah, Ph + (wm*32 + i*16)*48 + ks, 48);
                wmma::load_matrix_sync(fal, Pl + (wm*32 + i*16)*48 + ks, 48);
                #pragma unroll
                for (int j = 0; j < 2; j++) {
                    wmma::mma_sync(acc[i][j], fah, fbh[j], acc[i][j]);
                    wmma::mma_sync(acc[i][j], fah, fbl[j], acc[i][j]);
                    wmma::mma_sync(acc[i][j], fal, fbh[j], acc[i][j]);
                }
            }
        }
        __syncthreads();
    }

    float* ws = (float*)sm + w * (16*24);
    const int b = bh >> 4, h = bh & 15;
    #pragma unroll
    for (int i = 0; i < 2; i++) {
        #pragma unroll
        for (int j = 0; j < 2; j++) {
            wmma::store_matrix_sync(ws, acc[i][j], 24, wmma::mem_row_major);
            __syncwarp();
            #pragma unroll
            for (int tt = 0; tt < 8; tt++) {
                int e = lid + tt*32, r = e >> 4, c = e & 15;
                int m = bm + wm*32 + i*16 + r;
                int n = wn*32 + j*16 + c;
                g_O[((size_t)(b*L_ + m))*D_ + h*DH_ + n] = ws[r*24 + c];
            }
            __syncwarp();
        }
    }
}

// ============================================================================
extern "C" void kernel_launch(void* const* d_in, const int* in_sizes, int n_in,
                              void* d_out, int out_size)
{
    const float* q  = (const float*)d_in[0];
    const float* k  = (const float*)d_in[1];
    const float* v  = (const float*)d_in[2];
    const float* Wq = (const float*)d_in[3];
    const float* bq = (const float*)d_in[4];
    const float* Wk = (const float*)d_in[5];
    const float* bk = (const float*)d_in[6];
    const float* Wv = (const float*)d_in[7];
    const float* bv = (const float*)d_in[8];
    const float* Wo = (const float*)d_in[9];
    const float* bo = (const float*)d_in[10];
    float* out = (float*)d_out;

    float *pO, *pAttnFb;
    bf16 *pQh,*pQl,*pKh,*pKl,*pVh,*pVl,*pWth,*pWtl;
    cudaGetSymbolAddress((void**)&pO, g_O);
    cudaGetSymbolAddress((void**)&pAttnFb, g_attn_fallback);
    cudaGetSymbolAddress((void**)&pQh, g_Qh);
    cudaGetSymbolAddress((void**)&pQl, g_Ql);
    cudaGetSymbolAddress((void**)&pKh, g_Kh);
    cudaGetSymbolAddress((void**)&pKl, g_Kl);
    cudaGetSymbolAddress((void**)&pVh, g_Vh);
    cudaGetSymbolAddress((void**)&pVl, g_Vl);
    cudaGetSymbolAddress((void**)&pWth, g_Wth);
    cudaGetSymbolAddress((void**)&pWtl, g_Wtl);

    const long long need = (long long)M_ * D_ + (long long)BH_ * L_ * L_;
    float* attn = ((long long)out_size >= need) ? (out + (size_t)M_ * D_) : pAttnFb;

    const int SM_PROJ = 128*48*2*2 * 2;          // 49152
    const int SM_PV   = 128*48*2*2 + 32*80*2*2;  // 34816

    cudaFuncSetAttribute(proj_mma<0>, cudaFuncAttributeMaxDynamicSharedMemorySize, SM_PROJ);
    cudaFuncSetAttribute(proj_mma<2>, cudaFuncAttributeMaxDynamicSharedMemorySize, SM_PROJ);
    cudaFuncSetAttribute(scores_mma,  cudaFuncAttributeMaxDynamicSharedMemorySize, SM_PROJ);
    cudaFuncSetAttribute(pv_mma,      cudaFuncAttributeMaxDynamicSharedMemorySize, SM_PV);

    const size_t WSZ = (size_t)D_ * D_;
    dim3 gW(D_/32, D_/32);
    split_w_kernel<<<gW, 256>>>(Wq, pWth + 0*WSZ, pWtl + 0*WSZ);
    split_w_kernel<<<gW, 256>>>(Wk, pWth + 1*WSZ, pWtl + 1*WSZ);
    split_w_kernel<<<gW, 256>>>(Wv, pWth + 2*WSZ, pWtl + 2*WSZ);
    split_w_kernel<<<gW, 256>>>(Wo, pWth + 3*WSZ, pWtl + 3*WSZ);

    dim3 gProj(D_/128, M_/128);   // (8, 64)
    proj_mma<0><<<gProj, 256, SM_PROJ>>>(q, pWth + 0*WSZ, pWtl + 0*WSZ, bq, pQh, pQl, nullptr);
    proj_mma<0><<<gProj, 256, SM_PROJ>>>(k, pWth + 1*WSZ, pWtl + 1*WSZ, bk, pKh, pKl, nullptr);
    proj_mma<0><<<gProj, 256, SM_PROJ>>>(v, pWth + 2*WSZ, pWtl + 2*WSZ, bv, pVh, pVl, nullptr);

    dim3 gS(L_/128, L_/128, BH_); // (16,16,64)
    scores_mma<<<gS, 256, SM_PROJ>>>(attn);

    softmax_kernel<<<BH_*L_, 256>>>(attn);

    dim3 gPV(L_/128, BH_);        // (16, 64)
    pv_mma<<<gPV, 256, SM_PV>>>(attn);

    proj_mma<2><<<gProj, 256, SM_PROJ>>>(pO, pWth + 3*WSZ, pWtl + 3*WSZ, bo, nullptr, nullptr, out);
}